// round 1
// baseline (speedup 1.0000x reference)
#include <cuda_runtime.h>
#include <math.h>

#define D 128
#define NMAX 100000

// ---- scratch (static device globals; no allocation at kernel_launch time) ----
static __device__ float g_hW[(size_t)NMAX * D];   // 51.2 MB
static __device__ float g_agg[(size_t)NMAX * D];  // 51.2 MB
static __device__ float g_Wt1[256 * 384];         // [k][ r(128) | z(128) | xn(128) ] transposed
static __device__ float g_Wnh[128 * 128];         // [k][ hn(128) ] transposed
static __device__ float g_bias[512];              // br, bz, bxn, bhn

// ---------------------------------------------------------------------------
// Weight prep: fold (xr+hr) and (xz+hz) weight pairs, transpose for k-major
// streaming. gx = x @ w_ih^T  (w_ih[o][k], o<384, k<256)
// gh = h @ w_hh^T (h = x[:,128:256])
// ---------------------------------------------------------------------------
__global__ void prep_kernel(const float* __restrict__ w_ih, const float* __restrict__ w_hh,
                            const float* __restrict__ b_ih, const float* __restrict__ b_hh) {
    int idx = blockIdx.x * blockDim.x + threadIdx.x;
    int stride = gridDim.x * blockDim.x;
    for (int i = idx; i < 256 * 128; i += stride) {
        int k = i >> 7, d = i & 127;
        float hh_r = (k >= 128) ? w_hh[d * 128 + (k - 128)] : 0.f;
        float hh_z = (k >= 128) ? w_hh[(128 + d) * 128 + (k - 128)] : 0.f;
        g_Wt1[k * 384 + d]       = w_ih[d * 256 + k] + hh_r;
        g_Wt1[k * 384 + 128 + d] = w_ih[(128 + d) * 256 + k] + hh_z;
        g_Wt1[k * 384 + 256 + d] = w_ih[(256 + d) * 256 + k];
        if (k < 128) g_Wnh[k * 128 + d] = w_hh[(256 + d) * 128 + k];
    }
    for (int dd = idx; dd < 128; dd += stride) {
        g_bias[dd]       = b_ih[dd] + b_hh[dd];
        g_bias[128 + dd] = b_ih[128 + dd] + b_hh[128 + dd];
        g_bias[256 + dd] = b_ih[256 + dd];
        g_bias[384 + dd] = b_hh[256 + dd];
    }
}

__global__ void zero_kernel(int n_nodes) {
    size_t total = (size_t)n_nodes * (D / 4);
    float4* p = reinterpret_cast<float4*>(g_agg);
    for (size_t i = blockIdx.x * (size_t)blockDim.x + threadIdx.x; i < total;
         i += (size_t)gridDim.x * blockDim.x)
        p[i] = make_float4(0.f, 0.f, 0.f, 0.f);
}

// ---------------------------------------------------------------------------
// hW[n] = ent_embs[node_id[n]] @ W   (gathered 64x128 tile, W in smem)
// ---------------------------------------------------------------------------
#define HW_SMEM ((128 * 128 + 64 * 132) * 4)
__global__ __launch_bounds__(256) void hw_kernel(
        const float* __restrict__ ent, const int* __restrict__ node_id,
        const float* __restrict__ W, int n_nodes) {
    extern __shared__ float sm[];
    float* Ws = sm;              // 128*128 (row-major W[k][c])
    float* As = sm + 128 * 128;  // 64 rows * 132 (padded)
    int tid = threadIdx.x;
    int n0 = blockIdx.x * 64;
    for (int i = tid; i < 128 * 32; i += 256)
        reinterpret_cast<float4*>(Ws)[i] = __ldg(reinterpret_cast<const float4*>(W) + i);
    {
        int r = tid >> 2;
        int c0 = (tid & 3) * 8;  // float4 index
        int n = n0 + r;
        if (n < n_nodes) {
            const float4* src =
                reinterpret_cast<const float4*>(ent + (size_t)__ldg(node_id + n) * D);
            #pragma unroll
            for (int j = 0; j < 8; j++) {
                float4 v = __ldg(src + c0 + j);
                float* dst = As + r * 132 + (c0 + j) * 4;
                dst[0] = v.x; dst[1] = v.y; dst[2] = v.z; dst[3] = v.w;
            }
        } else {
            #pragma unroll
            for (int j = 0; j < 8; j++) {
                float* dst = As + r * 132 + (c0 + j) * 4;
                dst[0] = 0.f; dst[1] = 0.f; dst[2] = 0.f; dst[3] = 0.f;
            }
        }
    }
    __syncthreads();
    int r = tid >> 2;
    int cg = tid & 3;
    float acc[32];
    #pragma unroll
    for (int j = 0; j < 32; j++) acc[j] = 0.f;
    const float* arow = As + r * 132;
    const float4* wbase = reinterpret_cast<const float4*>(Ws) + cg * 8;
    #pragma unroll 4
    for (int k = 0; k < 128; k++) {
        float a = arow[k];
        const float4* wr = wbase + k * 32;
        #pragma unroll
        for (int j4 = 0; j4 < 8; j4++) {
            float4 w = wr[j4];
            acc[j4 * 4 + 0] = fmaf(a, w.x, acc[j4 * 4 + 0]);
            acc[j4 * 4 + 1] = fmaf(a, w.y, acc[j4 * 4 + 1]);
            acc[j4 * 4 + 2] = fmaf(a, w.z, acc[j4 * 4 + 2]);
            acc[j4 * 4 + 3] = fmaf(a, w.w, acc[j4 * 4 + 3]);
        }
    }
    int n = n0 + r;
    if (n < n_nodes) {
        float4* dst = reinterpret_cast<float4*>(g_hW + (size_t)n * D + cg * 32);
        #pragma unroll
        for (int j4 = 0; j4 < 8; j4++)
            dst[j4] = make_float4(acc[j4 * 4], acc[j4 * 4 + 1], acc[j4 * 4 + 2], acc[j4 * 4 + 3]);
    }
}

// ---------------------------------------------------------------------------
// Edge scatter: warp per edge, float4 vector atomics (sm_90+)
// ---------------------------------------------------------------------------
__global__ __launch_bounds__(256) void scatter_kernel(
        const int* __restrict__ esrc, const int* __restrict__ edst, int E) {
    int warp = (int)((blockIdx.x * (size_t)blockDim.x + threadIdx.x) >> 5);
    int lane = threadIdx.x & 31;
    if (warp >= E) return;
    int s = __ldg(esrc + warp);
    int d = __ldg(edst + warp);
    float4 v = __ldg(reinterpret_cast<const float4*>(g_hW + (size_t)s * D) + lane);
    atomicAdd(reinterpret_cast<float4*>(g_agg + (size_t)d * D) + lane, v);
}

// ---------------------------------------------------------------------------
// Fused GRU + relu + row-normalize.
// Block: 128 nodes, 256 threads. Thread (nl = t&127, q = t>>7) computes dims
// [q*64, q*64+64) of its node in 2 chunks of 32 using register accumulators.
// Weight loads are warp-uniform (L1 broadcast); X tile in padded smem.
// ---------------------------------------------------------------------------
#define EPI_SMEM ((256 * 129 + 128 * 129) * 4)
__global__ __launch_bounds__(256) void gru_kernel(
        const float* __restrict__ erb, const float* __restrict__ onorm,
        float* __restrict__ out, int n_nodes) {
    extern __shared__ float sm[];
    float* Xs = sm;              // [k=0..255][nl], stride 129
    float* Hs = sm + 256 * 129;  // [nl][d], stride 129
    __shared__ float s_part[256];
    int tid = threadIdx.x;
    int n0 = blockIdx.x * 128;
    // build X = [agg*out_norm | e_r_bias], transposed with pad
    for (int i = tid; i < 128 * 32; i += 256) {
        int nl = i >> 5;
        int c4 = i & 31;
        int n = n0 + nl;
        float4 a = make_float4(0.f, 0.f, 0.f, 0.f);
        float4 b = make_float4(0.f, 0.f, 0.f, 0.f);
        float sc = 0.f;
        if (n < n_nodes) {
            sc = __ldg(onorm + n);
            a = __ldg(reinterpret_cast<const float4*>(g_agg + (size_t)n * D) + c4);
            b = __ldg(reinterpret_cast<const float4*>(erb + (size_t)n * D) + c4);
        }
        int k = c4 * 4;
        Xs[(k + 0) * 129 + nl] = a.x * sc;
        Xs[(k + 1) * 129 + nl] = a.y * sc;
        Xs[(k + 2) * 129 + nl] = a.z * sc;
        Xs[(k + 3) * 129 + nl] = a.w * sc;
        Xs[(128 + k + 0) * 129 + nl] = b.x;
        Xs[(128 + k + 1) * 129 + nl] = b.y;
        Xs[(128 + k + 2) * 129 + nl] = b.z;
        Xs[(128 + k + 3) * 129 + nl] = b.w;
    }
    __syncthreads();
    int nl = tid & 127;
    int q = tid >> 7;
    float sumsq = 0.f;
    for (int chunk = 0; chunk < 2; chunk++) {
        int dbase = (q * 2 + chunk) * 32;
        // ---- pass A: r and z gates (K = 256 with folded weights) ----
        float ar[32], az[32];
        #pragma unroll
        for (int j = 0; j < 32; j++) { ar[j] = 0.f; az[j] = 0.f; }
        const float4* wr0 = reinterpret_cast<const float4*>(g_Wt1 + dbase);
        const float4* wz0 = reinterpret_cast<const float4*>(g_Wt1 + 128 + dbase);
        #pragma unroll 2
        for (int k = 0; k < 256; k++) {
            float x = Xs[k * 129 + nl];
            const float4* wr = wr0 + k * 96;
            const float4* wz = wz0 + k * 96;
            #pragma unroll
            for (int j4 = 0; j4 < 8; j4++) {
                float4 w = __ldg(wr + j4);
                ar[j4 * 4 + 0] = fmaf(x, w.x, ar[j4 * 4 + 0]);
                ar[j4 * 4 + 1] = fmaf(x, w.y, ar[j4 * 4 + 1]);
                ar[j4 * 4 + 2] = fmaf(x, w.z, ar[j4 * 4 + 2]);
                ar[j4 * 4 + 3] = fmaf(x, w.w, ar[j4 * 4 + 3]);
            }
            #pragma unroll
            for (int j4 = 0; j4 < 8; j4++) {
                float4 w = __ldg(wz + j4);
                az[j4 * 4 + 0] = fmaf(x, w.x, az[j4 * 4 + 0]);
                az[j4 * 4 + 1] = fmaf(x, w.y, az[j4 * 4 + 1]);
                az[j4 * 4 + 2] = fmaf(x, w.z, az[j4 * 4 + 2]);
                az[j4 * 4 + 3] = fmaf(x, w.w, az[j4 * 4 + 3]);
            }
        }
        float rg[32], zg[32];
        #pragma unroll
        for (int j = 0; j < 32; j++) {
            rg[j] = 1.f / (1.f + expf(-(ar[j] + g_bias[dbase + j])));
            zg[j] = 1.f / (1.f + expf(-(az[j] + g_bias[128 + dbase + j])));
        }
        // ---- pass B: xn (K=256) and hn (K=128, uses X[:,128:]) ----
        float axn[32], ahn[32];
        #pragma unroll
        for (int j = 0; j < 32; j++) { axn[j] = 0.f; ahn[j] = 0.f; }
        const float4* wn0 = reinterpret_cast<const float4*>(g_Wt1 + 256 + dbase);
        const float4* wh0 = reinterpret_cast<const float4*>(g_Wnh + dbase);
        #pragma unroll 2
        for (int k = 0; k < 128; k++) {
            float x = Xs[k * 129 + nl];
            const float4* wn = wn0 + k * 96;
            #pragma unroll
            for (int j4 = 0; j4 < 8; j4++) {
                float4 w = __ldg(wn + j4);
                axn[j4 * 4 + 0] = fmaf(x, w.x, axn[j4 * 4 + 0]);
                axn[j4 * 4 + 1] = fmaf(x, w.y, axn[j4 * 4 + 1]);
                axn[j4 * 4 + 2] = fmaf(x, w.z, axn[j4 * 4 + 2]);
                axn[j4 * 4 + 3] = fmaf(x, w.w, axn[j4 * 4 + 3]);
            }
        }
        #pragma unroll 2
        for (int k = 128; k < 256; k++) {
            float x = Xs[k * 129 + nl];
            const float4* wn = wn0 + k * 96;
            const float4* wh = wh0 + (k - 128) * 32;
            #pragma unroll
            for (int j4 = 0; j4 < 8; j4++) {
                float4 w = __ldg(wn + j4);
                axn[j4 * 4 + 0] = fmaf(x, w.x, axn[j4 * 4 + 0]);
                axn[j4 * 4 + 1] = fmaf(x, w.y, axn[j4 * 4 + 1]);
                axn[j4 * 4 + 2] = fmaf(x, w.z, axn[j4 * 4 + 2]);
                axn[j4 * 4 + 3] = fmaf(x, w.w, axn[j4 * 4 + 3]);
            }
            #pragma unroll
            for (int j4 = 0; j4 < 8; j4++) {
                float4 w = __ldg(wh + j4);
                ahn[j4 * 4 + 0] = fmaf(x, w.x, ahn[j4 * 4 + 0]);
                ahn[j4 * 4 + 1] = fmaf(x, w.y, ahn[j4 * 4 + 1]);
                ahn[j4 * 4 + 2] = fmaf(x, w.z, ahn[j4 * 4 + 2]);
                ahn[j4 * 4 + 3] = fmaf(x, w.w, ahn[j4 * 4 + 3]);
            }
        }
        // ---- combine: n gate, GRU output, relu ----
        #pragma unroll
        for (int j = 0; j < 32; j++) {
            int d = dbase + j;
            float nn = tanhf(axn[j] + g_bias[256 + d] + rg[j] * (ahn[j] + g_bias[384 + d]));
            float hp = Xs[(128 + d) * 129 + nl];
            float h = (1.f - zg[j]) * nn + zg[j] * hp;
            h = fmaxf(h, 0.f);
            sumsq += h * h;
            Hs[nl * 129 + d] = h;
        }
    }
    s_part[q * 128 + nl] = sumsq;
    __syncthreads();
    // ---- normalize + coalesced store ----
    for (int i = tid; i < 128 * 32; i += 256) {
        int nl2 = i >> 5;
        int c4 = i & 31;
        int n = n0 + nl2;
        if (n < n_nodes) {
            float norm = sqrtf(s_part[nl2] + s_part[128 + nl2]);
            float inv = 1.f / fmaxf(norm, 1e-12f);
            const float* hp = Hs + nl2 * 129 + c4 * 4;
            reinterpret_cast<float4*>(out + (size_t)n * D)[c4] =
                make_float4(hp[0] * inv, hp[1] * inv, hp[2] * inv, hp[3] * inv);
        }
    }
}

// ---------------------------------------------------------------------------
extern "C" void kernel_launch(void* const* d_in, const int* in_sizes, int n_in,
                              void* d_out, int out_size) {
    const float* ent   = (const float*)d_in[0];
    // d_in[1] = rel_embs (unused by reference)
    const float* erb   = (const float*)d_in[2];
    const float* onorm = (const float*)d_in[3];
    const float* Wn    = (const float*)d_in[4];
    const float* w_ih  = (const float*)d_in[5];
    const float* w_hh  = (const float*)d_in[6];
    const float* b_ih  = (const float*)d_in[7];
    const float* b_hh  = (const float*)d_in[8];
    const int* node_id = (const int*)d_in[9];
    const int* esrc    = (const int*)d_in[10];
    const int* edst    = (const int*)d_in[11];
    int N = in_sizes[3];    // out_norm has N elements
    int E = in_sizes[10];
    float* out = (float*)d_out;

    cudaFuncSetAttribute(hw_kernel, cudaFuncAttributeMaxDynamicSharedMemorySize, HW_SMEM);
    cudaFuncSetAttribute(gru_kernel, cudaFuncAttributeMaxDynamicSharedMemorySize, EPI_SMEM);

    prep_kernel<<<64, 256>>>(w_ih, w_hh, b_ih, b_hh);
    zero_kernel<<<512, 256>>>(N);
    hw_kernel<<<(N + 63) / 64, 256, HW_SMEM>>>(ent, node_id, Wn, N);
    scatter_kernel<<<(E + 7) / 8, 256>>>(esrc, edst, E);
    gru_kernel<<<(N + 127) / 128, 256, EPI_SMEM>>>(erb, onorm, out, N);
}

// round 2
// speedup vs baseline: 1.4622x; 1.4622x over previous
#include <cuda_runtime.h>
#include <math.h>

#define D 128
#define NMAX 100000

typedef unsigned long long ull;

// ---- scratch (static device globals) ----
static __device__ float g_hW[(size_t)NMAX * D];   // 51.2 MB
static __device__ float g_agg[(size_t)NMAX * D];  // 51.2 MB
static __device__ float g_Wt1[256 * 384];         // [k][ r(128) | z(128) | xn(128) ]
static __device__ float g_Wnh[128 * 128];         // [k][ hn(128) ]
static __device__ float g_bias[512];              // br, bz, bxn, bhn

// ---- f32x2 helpers ----
__device__ __forceinline__ void fma2(ull& acc, ull a, ull b) {
    asm("fma.rn.f32x2 %0, %1, %2, %0;" : "+l"(acc) : "l"(a), "l"(b));
}
__device__ __forceinline__ ull pack2(float x) {
    ull r; asm("mov.b64 %0, {%1, %1};" : "=l"(r) : "f"(x)); return r;
}
__device__ __forceinline__ void unpack2(ull v, float& lo, float& hi) {
    asm("mov.b64 {%0, %1}, %2;" : "=f"(lo), "=f"(hi) : "l"(v));
}
__device__ __forceinline__ float sigmoidf_(float x) { return 1.f / (1.f + expf(-x)); }

// ---------------------------------------------------------------------------
// Weight prep (unchanged from passing v1)
// ---------------------------------------------------------------------------
__global__ void prep_kernel(const float* __restrict__ w_ih, const float* __restrict__ w_hh,
                            const float* __restrict__ b_ih, const float* __restrict__ b_hh) {
    int idx = blockIdx.x * blockDim.x + threadIdx.x;
    int stride = gridDim.x * blockDim.x;
    for (int i = idx; i < 256 * 128; i += stride) {
        int k = i >> 7, d = i & 127;
        float hh_r = (k >= 128) ? w_hh[d * 128 + (k - 128)] : 0.f;
        float hh_z = (k >= 128) ? w_hh[(128 + d) * 128 + (k - 128)] : 0.f;
        g_Wt1[k * 384 + d]       = w_ih[d * 256 + k] + hh_r;
        g_Wt1[k * 384 + 128 + d] = w_ih[(128 + d) * 256 + k] + hh_z;
        g_Wt1[k * 384 + 256 + d] = w_ih[(256 + d) * 256 + k];
        if (k < 128) g_Wnh[k * 128 + d] = w_hh[(256 + d) * 128 + k];
    }
    for (int dd = idx; dd < 128; dd += stride) {
        g_bias[dd]       = b_ih[dd] + b_hh[dd];
        g_bias[128 + dd] = b_ih[128 + dd] + b_hh[128 + dd];
        g_bias[256 + dd] = b_ih[256 + dd];
        g_bias[384 + dd] = b_hh[256 + dd];
    }
}

__global__ void zero_kernel(int n_nodes) {
    size_t total = (size_t)n_nodes * (D / 4);
    float4* p = reinterpret_cast<float4*>(g_agg);
    for (size_t i = blockIdx.x * (size_t)blockDim.x + threadIdx.x; i < total;
         i += (size_t)gridDim.x * blockDim.x)
        p[i] = make_float4(0.f, 0.f, 0.f, 0.f);
}

// ---------------------------------------------------------------------------
// hW[n] = ent[node_id[n]] @ W.  64 nodes/block, 256 thr.
// Warp g owns dims [16g,16g+16); lane owns nodes (2*lane, 2*lane+1).
// X transposed in smem (Xh[k*66 + node]); W k-major from global (L1-resident).
// ---------------------------------------------------------------------------
#define HW_SMEM (128 * 66 * 4)   // 33.8 KB (reused for output staging 64*129)
__global__ __launch_bounds__(256, 2) void hw_kernel(
        const float* __restrict__ ent, const int* __restrict__ node_id,
        const float* __restrict__ W, int n_nodes) {
    extern __shared__ float sm[];
    __shared__ int sid[64];
    int tid = threadIdx.x;
    int n0 = blockIdx.x * 64;
    if (tid < 64) {
        int n = n0 + tid;
        sid[tid] = (n < n_nodes) ? __ldg(node_id + n) : -1;
    }
    __syncthreads();
    // gather: thread (r = tid&63, q = tid>>6) loads 128B chunk q of row r
    {
        int r = tid & 63;
        int q = tid >> 6;
        int row = sid[r];
        #pragma unroll
        for (int j = 0; j < 8; j++) {
            int c4 = q * 8 + j;
            float4 v = (row >= 0)
                ? __ldg(reinterpret_cast<const float4*>(ent) + (size_t)row * 32 + c4)
                : make_float4(0.f, 0.f, 0.f, 0.f);
            sm[(4 * c4 + 0) * 66 + r] = v.x;
            sm[(4 * c4 + 1) * 66 + r] = v.y;
            sm[(4 * c4 + 2) * 66 + r] = v.z;
            sm[(4 * c4 + 3) * 66 + r] = v.w;
        }
    }
    __syncthreads();
    int lane = tid & 31;
    int g = tid >> 5;
    int dbase = g * 16;
    const float2* Xs2 = reinterpret_cast<const float2*>(sm);
    ull accA[8], accB[8];
    #pragma unroll
    for (int p = 0; p < 8; p++) { accA[p] = 0ull; accB[p] = 0ull; }
    #pragma unroll 2
    for (int k = 0; k < 128; k++) {
        float2 x2 = Xs2[k * 33 + lane];
        ull xA = pack2(x2.x), xB = pack2(x2.y);
        const ulonglong2* wp = reinterpret_cast<const ulonglong2*>(W + (size_t)k * 128 + dbase);
        #pragma unroll
        for (int c = 0; c < 4; c++) {
            ulonglong2 wv = __ldg(wp + c);
            fma2(accA[2 * c], wv.x, xA); fma2(accA[2 * c + 1], wv.y, xA);
            fma2(accB[2 * c], wv.x, xB); fma2(accB[2 * c + 1], wv.y, xB);
        }
    }
    __syncthreads();   // done reading Xs; reuse smem as output stage [node*129 + d]
    int nA = 2 * lane, nB = 2 * lane + 1;
    #pragma unroll
    for (int p = 0; p < 8; p++) {
        float a0, a1, b0, b1;
        unpack2(accA[p], a0, a1);
        unpack2(accB[p], b0, b1);
        int d = dbase + 2 * p;
        sm[nA * 129 + d] = a0; sm[nA * 129 + d + 1] = a1;
        sm[nB * 129 + d] = b0; sm[nB * 129 + d + 1] = b1;
    }
    __syncthreads();
    for (int i = tid; i < 64 * 32; i += 256) {
        int c4 = i & 31, nl = i >> 5;
        int n = n0 + nl;
        if (n < n_nodes) {
            const float* hp = sm + nl * 129 + c4 * 4;
            reinterpret_cast<float4*>(g_hW + (size_t)n * D)[c4] =
                make_float4(hp[0], hp[1], hp[2], hp[3]);
        }
    }
}

// ---------------------------------------------------------------------------
// Edge scatter: warp per edge, float4 vector atomics
// ---------------------------------------------------------------------------
__global__ __launch_bounds__(256) void scatter_kernel(
        const int* __restrict__ esrc, const int* __restrict__ edst, int E) {
    int warp = (int)((blockIdx.x * (size_t)blockDim.x + threadIdx.x) >> 5);
    int lane = threadIdx.x & 31;
    if (warp >= E) return;
    int s = __ldg(esrc + warp);
    int d = __ldg(edst + warp);
    float4 v = __ldg(reinterpret_cast<const float4*>(g_hW + (size_t)s * D) + lane);
    atomicAdd(reinterpret_cast<float4*>(g_agg + (size_t)d * D) + lane, v);
}

// ---------------------------------------------------------------------------
// Fused GRU + relu + normalize.  64 nodes/block, 256 thr, 2 blocks/SM.
// Warp g owns dims [16g,16g+16); lane owns nodes (2*lane, 2*lane+1).
// Xs transposed smem [k*66 + node] (k=0..255), Hs [node*129 + d].
// ---------------------------------------------------------------------------
#define GRU_XS   (256 * 66)                       // floats
#define GRU_SMEM ((GRU_XS + 64 * 129) * 4)        // ~100.6 KB
__global__ __launch_bounds__(256, 2) void gru_kernel(
        const float* __restrict__ erb, const float* __restrict__ onorm,
        float* __restrict__ out, int n_nodes) {
    extern __shared__ float sm[];
    float* XsF = sm;
    float* Hs = sm + GRU_XS;
    __shared__ float s_part[512];
    int tid = threadIdx.x;
    int n0 = blockIdx.x * 64;
    // build X = [agg*out_norm | e_r_bias], transposed
    for (int i = tid; i < 64 * 32; i += 256) {
        int c4 = i >> 6, nl = i & 63;
        int n = n0 + nl;
        float4 a = make_float4(0.f, 0.f, 0.f, 0.f);
        float4 b = make_float4(0.f, 0.f, 0.f, 0.f);
        float sc = 0.f;
        if (n < n_nodes) {
            sc = __ldg(onorm + n);
            a = __ldg(reinterpret_cast<const float4*>(g_agg) + (size_t)n * 32 + c4);
            b = __ldg(reinterpret_cast<const float4*>(erb) + (size_t)n * 32 + c4);
        }
        int k = 4 * c4;
        XsF[(k + 0) * 66 + nl] = a.x * sc;
        XsF[(k + 1) * 66 + nl] = a.y * sc;
        XsF[(k + 2) * 66 + nl] = a.z * sc;
        XsF[(k + 3) * 66 + nl] = a.w * sc;
        XsF[(128 + k + 0) * 66 + nl] = b.x;
        XsF[(128 + k + 1) * 66 + nl] = b.y;
        XsF[(128 + k + 2) * 66 + nl] = b.z;
        XsF[(128 + k + 3) * 66 + nl] = b.w;
    }
    __syncthreads();
    int lane = tid & 31;
    int g = tid >> 5;
    int dbase = g * 16;
    int nA = 2 * lane, nB = 2 * lane + 1;
    const float2* Xs2 = reinterpret_cast<const float2*>(sm);

    // ---- pass A: r and z gates (K=256, folded weights) ----
    ull arA[8], azA[8], arB[8], azB[8];
    #pragma unroll
    for (int p = 0; p < 8; p++) { arA[p] = azA[p] = arB[p] = azB[p] = 0ull; }
    #pragma unroll 2
    for (int k = 0; k < 256; k++) {
        float2 x2 = Xs2[k * 33 + lane];
        ull xA = pack2(x2.x), xB = pack2(x2.y);
        const ulonglong2* wr = reinterpret_cast<const ulonglong2*>(g_Wt1 + (size_t)k * 384 + dbase);
        const ulonglong2* wz = reinterpret_cast<const ulonglong2*>(g_Wt1 + (size_t)k * 384 + 128 + dbase);
        #pragma unroll
        for (int c = 0; c < 4; c++) {
            ulonglong2 wv = __ldg(wr + c);
            fma2(arA[2 * c], wv.x, xA); fma2(arA[2 * c + 1], wv.y, xA);
            fma2(arB[2 * c], wv.x, xB); fma2(arB[2 * c + 1], wv.y, xB);
        }
        #pragma unroll
        for (int c = 0; c < 4; c++) {
            ulonglong2 wv = __ldg(wz + c);
            fma2(azA[2 * c], wv.x, xA); fma2(azA[2 * c + 1], wv.y, xA);
            fma2(azB[2 * c], wv.x, xB); fma2(azB[2 * c + 1], wv.y, xB);
        }
    }
    float rgA[16], zgA[16], rgB[16], zgB[16];
    #pragma unroll
    for (int p = 0; p < 8; p++) {
        int d = dbase + 2 * p;
        float br0 = __ldg(g_bias + d), br1 = __ldg(g_bias + d + 1);
        float bz0 = __ldg(g_bias + 128 + d), bz1 = __ldg(g_bias + 128 + d + 1);
        float a0, a1;
        unpack2(arA[p], a0, a1); rgA[2 * p] = sigmoidf_(a0 + br0); rgA[2 * p + 1] = sigmoidf_(a1 + br1);
        unpack2(arB[p], a0, a1); rgB[2 * p] = sigmoidf_(a0 + br0); rgB[2 * p + 1] = sigmoidf_(a1 + br1);
        unpack2(azA[p], a0, a1); zgA[2 * p] = sigmoidf_(a0 + bz0); zgA[2 * p + 1] = sigmoidf_(a1 + bz1);
        unpack2(azB[p], a0, a1); zgB[2 * p] = sigmoidf_(a0 + bz0); zgB[2 * p + 1] = sigmoidf_(a1 + bz1);
    }

    // ---- pass B: xn (K=256) and hn (K=128 over X[:,128:]) ----
    ull xnA[8], xnB[8], hnA[8], hnB[8];
    #pragma unroll
    for (int p = 0; p < 8; p++) { xnA[p] = xnB[p] = hnA[p] = hnB[p] = 0ull; }
    #pragma unroll 2
    for (int k = 0; k < 128; k++) {
        float2 x2 = Xs2[k * 33 + lane];
        ull xA = pack2(x2.x), xB = pack2(x2.y);
        const ulonglong2* wn = reinterpret_cast<const ulonglong2*>(g_Wt1 + (size_t)k * 384 + 256 + dbase);
        #pragma unroll
        for (int c = 0; c < 4; c++) {
            ulonglong2 wv = __ldg(wn + c);
            fma2(xnA[2 * c], wv.x, xA); fma2(xnA[2 * c + 1], wv.y, xA);
            fma2(xnB[2 * c], wv.x, xB); fma2(xnB[2 * c + 1], wv.y, xB);
        }
    }
    #pragma unroll 2
    for (int k = 128; k < 256; k++) {
        float2 x2 = Xs2[k * 33 + lane];
        ull xA = pack2(x2.x), xB = pack2(x2.y);
        const ulonglong2* wn = reinterpret_cast<const ulonglong2*>(g_Wt1 + (size_t)k * 384 + 256 + dbase);
        const ulonglong2* wh = reinterpret_cast<const ulonglong2*>(g_Wnh + (size_t)(k - 128) * 128 + dbase);
        #pragma unroll
        for (int c = 0; c < 4; c++) {
            ulonglong2 wv = __ldg(wn + c);
            fma2(xnA[2 * c], wv.x, xA); fma2(xnA[2 * c + 1], wv.y, xA);
            fma2(xnB[2 * c], wv.x, xB); fma2(xnB[2 * c + 1], wv.y, xB);
        }
        #pragma unroll
        for (int c = 0; c < 4; c++) {
            ulonglong2 wv = __ldg(wh + c);
            fma2(hnA[2 * c], wv.x, xA); fma2(hnA[2 * c + 1], wv.y, xA);
            fma2(hnB[2 * c], wv.x, xB); fma2(hnB[2 * c + 1], wv.y, xB);
        }
    }

    // ---- combine: n gate, GRU output, relu; stage h in Hs ----
    float ssA = 0.f, ssB = 0.f;
    #pragma unroll
    for (int p = 0; p < 8; p++) {
        int d = dbase + 2 * p;
        float bn0 = __ldg(g_bias + 256 + d), bn1 = __ldg(g_bias + 256 + d + 1);
        float bh0 = __ldg(g_bias + 384 + d), bh1 = __ldg(g_bias + 384 + d + 1);
        float x0, x1, h0, h1;
        // node A
        unpack2(xnA[p], x0, x1);
        unpack2(hnA[p], h0, h1);
        {
            float nn0 = tanhf(x0 + bn0 + rgA[2 * p] * (h0 + bh0));
            float nn1 = tanhf(x1 + bn1 + rgA[2 * p + 1] * (h1 + bh1));
            float hp0 = XsF[(128 + d) * 66 + nA];
            float hp1 = XsF[(128 + d + 1) * 66 + nA];
            float z0 = zgA[2 * p], z1 = zgA[2 * p + 1];
            float r0 = fmaxf((1.f - z0) * nn0 + z0 * hp0, 0.f);
            float r1 = fmaxf((1.f - z1) * nn1 + z1 * hp1, 0.f);
            ssA += r0 * r0 + r1 * r1;
            Hs[nA * 129 + d] = r0; Hs[nA * 129 + d + 1] = r1;
        }
        // node B
        unpack2(xnB[p], x0, x1);
        unpack2(hnB[p], h0, h1);
        {
            float nn0 = tanhf(x0 + bn0 + rgB[2 * p] * (h0 + bh0));
            float nn1 = tanhf(x1 + bn1 + rgB[2 * p + 1] * (h1 + bh1));
            float hp0 = XsF[(128 + d) * 66 + nB];
            float hp1 = XsF[(128 + d + 1) * 66 + nB];
            float z0 = zgB[2 * p], z1 = zgB[2 * p + 1];
            float r0 = fmaxf((1.f - z0) * nn0 + z0 * hp0, 0.f);
            float r1 = fmaxf((1.f - z1) * nn1 + z1 * hp1, 0.f);
            ssB += r0 * r0 + r1 * r1;
            Hs[nB * 129 + d] = r0; Hs[nB * 129 + d + 1] = r1;
        }
    }
    s_part[g * 64 + nA] = ssA;
    s_part[g * 64 + nB] = ssB;
    __syncthreads();
    // ---- normalize + coalesced store ----
    for (int i = tid; i < 64 * 32; i += 256) {
        int c4 = i & 31, nl = i >> 5;
        int n = n0 + nl;
        if (n < n_nodes) {
            float tot = 0.f;
            #pragma unroll
            for (int j = 0; j < 8; j++) tot += s_part[j * 64 + nl];
            float inv = 1.f / fmaxf(sqrtf(tot), 1e-12f);
            const float* hp = Hs + nl * 129 + c4 * 4;
            reinterpret_cast<float4*>(out + (size_t)n * D)[c4] =
                make_float4(hp[0] * inv, hp[1] * inv, hp[2] * inv, hp[3] * inv);
        }
    }
}

// ---------------------------------------------------------------------------
extern "C" void kernel_launch(void* const* d_in, const int* in_sizes, int n_in,
                              void* d_out, int out_size) {
    const float* ent   = (const float*)d_in[0];
    const float* erb   = (const float*)d_in[2];
    const float* onorm = (const float*)d_in[3];
    const float* Wn    = (const float*)d_in[4];
    const float* w_ih  = (const float*)d_in[5];
    const float* w_hh  = (const float*)d_in[6];
    const float* b_ih  = (const float*)d_in[7];
    const float* b_hh  = (const float*)d_in[8];
    const int* node_id = (const int*)d_in[9];
    const int* esrc    = (const int*)d_in[10];
    const int* edst    = (const int*)d_in[11];
    int N = in_sizes[3];
    int E = in_sizes[10];
    float* out = (float*)d_out;

    cudaFuncSetAttribute(hw_kernel, cudaFuncAttributeMaxDynamicSharedMemorySize, HW_SMEM);
    cudaFuncSetAttribute(gru_kernel, cudaFuncAttributeMaxDynamicSharedMemorySize, GRU_SMEM);

    prep_kernel<<<64, 256>>>(w_ih, w_hh, b_ih, b_hh);
    zero_kernel<<<512, 256>>>(N);
    hw_kernel<<<(N + 63) / 64, 256, HW_SMEM>>>(ent, node_id, Wn, N);
    scatter_kernel<<<(E + 7) / 8, 256>>>(esrc, edst, E);
    gru_kernel<<<(N + 63) / 64, 256, GRU_SMEM>>>(erb, onorm, out, N);
}

// round 4
// speedup vs baseline: 5.6594x; 3.8703x over previous
#include <cuda_runtime.h>
#include <cuda_bf16.h>
#include <cstdint>
#include <math.h>

#define D 128
#define NMAX 100000
#define NPAD_MAX 100096

// ---- scratch (static device globals; no runtime allocation) ----
static __device__ float g_h[(size_t)NMAX * D];                  // gathered ent rows
static __device__ float g_agg[(size_t)NMAX * D];                // scatter-sum of g_h
static __device__ __nv_bfloat16 g_Xhi[(size_t)NPAD_MAX * 256];  // X hi split
static __device__ __nv_bfloat16 g_Xlo[(size_t)NPAD_MAX * 256];  // X lo split
static __device__ __nv_bfloat16 g_B[512 * 768];                 // [n][ Bhi | Bhi | Blo ]
static __device__ float g_C[(size_t)NPAD_MAX * 512];            // GEMM result (gate preacts)
static __device__ float g_bias[512];                            // br, bz, bxn, bhh_n

// ============================ PTX helpers (plain sm_103; no 'a' features) ============
__device__ __forceinline__ uint32_t smem_u32(const void* p) {
    uint32_t a;
    asm("{ .reg .u64 t; cvta.to.shared.u64 t, %1; cvt.u32.u64 %0, t; }" : "=r"(a) : "l"(p));
    return a;
}
__device__ __forceinline__ void cp_async16(uint32_t dst, const void* src) {
    asm volatile("cp.async.cg.shared.global [%0], [%1], 16;" :: "r"(dst), "l"(src));
}
__device__ __forceinline__ void ldm_x4(uint32_t* r, uint32_t addr) {
    asm volatile("ldmatrix.sync.aligned.m8n8.x4.shared.b16 {%0,%1,%2,%3}, [%4];"
                 : "=r"(r[0]), "=r"(r[1]), "=r"(r[2]), "=r"(r[3]) : "r"(addr));
}
__device__ __forceinline__ void mma_bf16(float* c, const uint32_t* a, uint32_t b0, uint32_t b1) {
    asm volatile(
        "mma.sync.aligned.m16n8k16.row.col.f32.bf16.bf16.f32 "
        "{%0,%1,%2,%3}, {%4,%5,%6,%7}, {%8,%9}, {%0,%1,%2,%3};"
        : "+f"(c[0]), "+f"(c[1]), "+f"(c[2]), "+f"(c[3])
        : "r"(a[0]), "r"(a[1]), "r"(a[2]), "r"(a[3]), "r"(b0), "r"(b1));
}
__device__ __forceinline__ float sigmoidf_(float x) { return 1.f / (1.f + expf(-x)); }

// ============================ prep: folded B (bf16 hi/lo) + biases ============================
// B0[n][k], n = gate*128+d (r|z|xn|hn), k<256:
//  n<384: k<128: Sum_j W[k][j]*w_ih[n][j] (fold of neighbor weight)
//         k>=128: w_ih[n][k] + (n<256 ? w_hh[n][k-128] : 0)
//  n>=384 (hn): k<128: 0 ; k>=128: w_hh[(n-128)][k-128]
__global__ void prep_kernel(const float* __restrict__ W, const float* __restrict__ w_ih,
                            const float* __restrict__ w_hh, const float* __restrict__ b_ih,
                            const float* __restrict__ b_hh) {
    int n = blockIdx.x;
    int k = threadIdx.x;
    if (n == 512) {
        if (k < 128) {
            g_bias[k]       = b_ih[k] + b_hh[k];
            g_bias[128 + k] = b_ih[128 + k] + b_hh[128 + k];
            g_bias[256 + k] = b_ih[256 + k];
            g_bias[384 + k] = b_hh[256 + k];
        }
        return;
    }
    float v;
    if (k < 128) {
        if (n < 384) {
            float acc = 0.f;
            for (int j = 0; j < 128; j++) acc = fmaf(W[k * 128 + j], w_ih[n * 256 + j], acc);
            v = acc;
        } else v = 0.f;
    } else {
        if (n < 256)      v = w_ih[n * 256 + k] + w_hh[n * 128 + (k - 128)];
        else if (n < 384) v = w_ih[n * 256 + k];
        else              v = w_hh[(n - 128) * 128 + (k - 128)];
    }
    __nv_bfloat16 hi = __float2bfloat16_rn(v);
    __nv_bfloat16 lo = __float2bfloat16_rn(v - __bfloat162float(hi));
    g_B[n * 768 + k] = hi;
    g_B[n * 768 + 256 + k] = hi;
    g_B[n * 768 + 512 + k] = lo;
}

// ============================ gather / zero / scatter ============================
__global__ __launch_bounds__(256) void gather_kernel(const float* __restrict__ ent,
                                                     const int* __restrict__ node_id, int N) {
    int i = blockIdx.x * blockDim.x + threadIdx.x;
    int node = i >> 5, lane = i & 31;
    if (node >= N) return;
    int row = __ldg(node_id + node);
    reinterpret_cast<float4*>(g_h)[(size_t)node * 32 + lane] =
        __ldg(reinterpret_cast<const float4*>(ent) + (size_t)row * 32 + lane);
}

__global__ void zero_kernel(int N) {
    size_t total = (size_t)N * 32;
    float4* p = reinterpret_cast<float4*>(g_agg);
    for (size_t i = blockIdx.x * (size_t)blockDim.x + threadIdx.x; i < total;
         i += (size_t)gridDim.x * blockDim.x)
        p[i] = make_float4(0.f, 0.f, 0.f, 0.f);
}

__global__ __launch_bounds__(256) void scatter_kernel(const int* __restrict__ esrc,
                                                      const int* __restrict__ edst, int E) {
    int warp = (int)((blockIdx.x * (size_t)blockDim.x + threadIdx.x) >> 5);
    int lane = threadIdx.x & 31;
    if (warp >= E) return;
    int s = __ldg(esrc + warp);
    int d = __ldg(edst + warp);
    float4 v = __ldg(reinterpret_cast<const float4*>(g_h) + (size_t)s * 32 + lane);
    atomicAdd(reinterpret_cast<float4*>(g_agg) + (size_t)d * 32 + lane, v);
}

// ============================ build X (hi/lo bf16 split) ============================
__global__ __launch_bounds__(256) void build_x_kernel(const float* __restrict__ erb,
                                                      const float* __restrict__ onorm,
                                                      int N, int npad) {
    int i = blockIdx.x * blockDim.x + threadIdx.x;
    int node = i >> 5, lane = i & 31;
    if (node >= npad) return;
    float x[8];
    if (node < N) {
        float sc = __ldg(onorm + node);
        float4 a = __ldg(reinterpret_cast<const float4*>(g_agg) + (size_t)node * 32 + lane);
        float4 e = __ldg(reinterpret_cast<const float4*>(erb) + (size_t)node * 32 + lane);
        x[0] = a.x * sc; x[1] = a.y * sc; x[2] = a.z * sc; x[3] = a.w * sc;
        x[4] = e.x; x[5] = e.y; x[6] = e.z; x[7] = e.w;
    } else {
        #pragma unroll
        for (int q = 0; q < 8; q++) x[q] = 0.f;
    }
    unsigned short hs[8], ls[8];
    #pragma unroll
    for (int q = 0; q < 8; q++) {
        __nv_bfloat16 hb = __float2bfloat16_rn(x[q]);
        __nv_bfloat16 lb = __float2bfloat16_rn(x[q] - __bfloat162float(hb));
        hs[q] = *reinterpret_cast<unsigned short*>(&hb);
        ls[q] = *reinterpret_cast<unsigned short*>(&lb);
    }
    uint2* dhi0 = reinterpret_cast<uint2*>(g_Xhi + (size_t)node * 256 + lane * 4);
    uint2* dhi1 = reinterpret_cast<uint2*>(g_Xhi + (size_t)node * 256 + 128 + lane * 4);
    uint2* dlo0 = reinterpret_cast<uint2*>(g_Xlo + (size_t)node * 256 + lane * 4);
    uint2* dlo1 = reinterpret_cast<uint2*>(g_Xlo + (size_t)node * 256 + 128 + lane * 4);
    *dhi0 = make_uint2((uint32_t)hs[0] | ((uint32_t)hs[1] << 16), (uint32_t)hs[2] | ((uint32_t)hs[3] << 16));
    *dhi1 = make_uint2((uint32_t)hs[4] | ((uint32_t)hs[5] << 16), (uint32_t)hs[6] | ((uint32_t)hs[7] << 16));
    *dlo0 = make_uint2((uint32_t)ls[0] | ((uint32_t)ls[1] << 16), (uint32_t)ls[2] | ((uint32_t)ls[3] << 16));
    *dlo1 = make_uint2((uint32_t)ls[4] | ((uint32_t)ls[5] << 16), (uint32_t)ls[6] | ((uint32_t)ls[7] << 16));
}

// ============================ GEMM: C[npad,512] = Xv[npad,768] @ Bv[768,512]^T =========
// Virtual K: chunks 0-3 = Xhi·Bhi, 4-7 = Xlo·Bhi, 8-11 = Xhi·Blo (stitched in g_B).
// BM=128, BN=128, BK=64, 3-stage cp.async pipeline, 8 warps, warp tile 32x64.
#define STAGE_BYTES 32768
#define GEMM_SMEM (3 * STAGE_BYTES)

__global__ __launch_bounds__(256, 1) void gemm_kernel(int npad) {
    extern __shared__ char smc[];
    uint32_t sbase = smem_u32(smc);
    int tid = threadIdx.x, lane = tid & 31, w = tid >> 5;
    int n0 = blockIdx.x * 128;          // node rows
    int d0 = blockIdx.y * 128;          // output cols
    int wm = w & 3, wn = w >> 2;
    int m0 = wm * 32, nw0 = wn * 64;

    float acc[2][8][4];
    #pragma unroll
    for (int a = 0; a < 2; a++)
        #pragma unroll
        for (int b = 0; b < 8; b++)
            #pragma unroll
            for (int c = 0; c < 4; c++) acc[a][b][c] = 0.f;

    // chunk loader: A tile 128x64 from Xhi/Xlo, B tile 128x64 from g_B
    auto load_chunk = [&](int c, int st) {
        const __nv_bfloat16* X = (c >= 4 && c < 8) ? g_Xlo : g_Xhi;
        const __nv_bfloat16* Asrc = X + (size_t)n0 * 256 + (c & 3) * 64;
        const __nv_bfloat16* Bsrc = g_B + (size_t)d0 * 768 + c * 64;
        uint32_t abase = sbase + st * STAGE_BYTES;
        uint32_t bbase = abase + 16384;
        #pragma unroll
        for (int i = 0; i < 4; i++) {
            int e = i * 256 + tid;
            int row = e >> 3, ch = e & 7;
            cp_async16(abase + (row * 8 + (ch ^ (row & 7))) * 16,
                       Asrc + (size_t)row * 256 + ch * 8);
        }
        #pragma unroll
        for (int i = 0; i < 4; i++) {
            int e = i * 256 + tid;
            int row = e >> 3, ch = e & 7;
            cp_async16(bbase + (row * 8 + (ch ^ (row & 7))) * 16,
                       Bsrc + (size_t)row * 768 + ch * 8);
        }
        asm volatile("cp.async.commit_group;" ::: "memory");
    };

    load_chunk(0, 0);
    load_chunk(1, 1);

    for (int c = 0; c < 12; c++) {
        int st = c % 3;
        if (c < 10) asm volatile("cp.async.wait_group 1;" ::: "memory");
        else        asm volatile("cp.async.wait_group 0;" ::: "memory");
        __syncthreads();
        uint32_t abase = sbase + st * STAGE_BYTES;
        uint32_t bbase = abase + 16384;
        #pragma unroll
        for (int k16 = 0; k16 < 4; k16++) {
            uint32_t af[2][4], bf[4][4];
            #pragma unroll
            for (int mi = 0; mi < 2; mi++) {
                int row = m0 + mi * 16 + (lane & 15);
                int ch = k16 * 2 + (lane >> 4);
                ldm_x4(af[mi], abase + (row * 8 + (ch ^ (row & 7))) * 16);
            }
            #pragma unroll
            for (int j = 0; j < 4; j++) {
                int row = nw0 + j * 16 + (lane & 15);
                int ch = k16 * 2 + (lane >> 4);
                ldm_x4(bf[j], bbase + (row * 8 + (ch ^ (row & 7))) * 16);
            }
            #pragma unroll
            for (int mi = 0; mi < 2; mi++)
                #pragma unroll
                for (int j = 0; j < 4; j++) {
                    mma_bf16(acc[mi][2 * j],     af[mi], bf[j][0], bf[j][2]);
                    mma_bf16(acc[mi][2 * j + 1], af[mi], bf[j][1], bf[j][3]);
                }
        }
        __syncthreads();
        if (c + 2 < 12) load_chunk(c + 2, (c + 2) % 3);
    }

    // write C
    int tr = lane >> 2, tc = (lane & 3) * 2;
    #pragma unroll
    for (int mi = 0; mi < 2; mi++) {
        #pragma unroll
        for (int j = 0; j < 8; j++) {
            int node = n0 + m0 + mi * 16 + tr;
            int d = d0 + nw0 + j * 8 + tc;
            float* cp = acc[mi][j];
            *reinterpret_cast<float2*>(g_C + (size_t)node * 512 + d) =
                make_float2(cp[0], cp[1]);
            *reinterpret_cast<float2*>(g_C + (size_t)(node + 8) * 512 + d) =
                make_float2(cp[2], cp[3]);
        }
    }
}

// ============================ epilogue: gates + relu + row norm ============================
__global__ __launch_bounds__(256) void epilogue_kernel(const float* __restrict__ erb,
                                                       float* __restrict__ out, int N) {
    int gw = (int)((blockIdx.x * (size_t)blockDim.x + threadIdx.x) >> 5);
    int lane = threadIdx.x & 31;
    if (gw >= N) return;
    const float4* C4 = reinterpret_cast<const float4*>(g_C + (size_t)gw * 512);
    float4 r4 = __ldg(C4 + lane);
    float4 z4 = __ldg(C4 + 32 + lane);
    float4 x4 = __ldg(C4 + 64 + lane);
    float4 h4 = __ldg(C4 + 96 + lane);
    float4 e4 = __ldg(reinterpret_cast<const float4*>(erb) + (size_t)gw * 32 + lane);
    const float* rr = &r4.x;
    const float* zz = &z4.x;
    const float* xx = &x4.x;
    const float* hh = &h4.x;
    const float* ee = &e4.x;
    float hv[4];
    float ss = 0.f;
    #pragma unroll
    for (int i = 0; i < 4; i++) {
        int d = lane * 4 + i;
        float r = sigmoidf_(rr[i] + __ldg(g_bias + d));
        float z = sigmoidf_(zz[i] + __ldg(g_bias + 128 + d));
        float nn = tanhf(xx[i] + __ldg(g_bias + 256 + d) + r * (hh[i] + __ldg(g_bias + 384 + d)));
        float h = fmaxf((1.f - z) * nn + z * ee[i], 0.f);
        ss += h * h;
        hv[i] = h;
    }
    #pragma unroll
    for (int o = 16; o; o >>= 1) ss += __shfl_xor_sync(0xFFFFFFFFu, ss, o);
    float inv = 1.f / fmaxf(sqrtf(ss), 1e-12f);
    reinterpret_cast<float4*>(out)[(size_t)gw * 32 + lane] =
        make_float4(hv[0] * inv, hv[1] * inv, hv[2] * inv, hv[3] * inv);
}

// ============================ launch ============================
extern "C" void kernel_launch(void* const* d_in, const int* in_sizes, int n_in,
                              void* d_out, int out_size) {
    const float* ent   = (const float*)d_in[0];
    const float* erb   = (const float*)d_in[2];
    const float* onorm = (const float*)d_in[3];
    const float* Wn    = (const float*)d_in[4];
    const float* w_ih  = (const float*)d_in[5];
    const float* w_hh  = (const float*)d_in[6];
    const float* b_ih  = (const float*)d_in[7];
    const float* b_hh  = (const float*)d_in[8];
    const int* node_id = (const int*)d_in[9];
    const int* esrc    = (const int*)d_in[10];
    const int* edst    = (const int*)d_in[11];
    int N = in_sizes[3];
    int E = in_sizes[10];
    float* out = (float*)d_out;
    int npad = ((N + 127) / 128) * 128;
    if (npad > NPAD_MAX) npad = NPAD_MAX;

    cudaFuncSetAttribute(gemm_kernel, cudaFuncAttributeMaxDynamicSharedMemorySize, GEMM_SMEM);

    prep_kernel<<<513, 256>>>(Wn, w_ih, w_hh, b_ih, b_hh);
    gather_kernel<<<(N * 32 + 255) / 256, 256>>>(ent, node_id, N);
    zero_kernel<<<512, 256>>>(N);
    scatter_kernel<<<(E + 7) / 8, 256>>>(esrc, edst, E);
    build_x_kernel<<<(npad * 32 + 255) / 256, 256>>>(erb, onorm, N, npad);
    dim3 ggrid(npad / 128, 4);
    gemm_kernel<<<ggrid, 256, GEMM_SMEM>>>(npad);
    epilogue_kernel<<<(N * 32 + 255) / 256, 256>>>(erb, out, N);
}